// round 2
// baseline (speedup 1.0000x reference)
#include <cuda_runtime.h>

// Problem constants
#define NNODES 200000
#define FDIM   602
#define DADJ   128
#define HDIM   256
#define NCLS   41
#define NB     1024
#define S1N    25
#define S2N    10
#define NH0    (NB * S2N)   // 10240
#define H2     (2 * HDIM)   // 512

// ---------------------------------------------------------------------------
// Scratch (allocation-free: __device__ globals, referenced directly from
// device code — kernel_launch makes NO runtime API calls besides launches,
// so it is trivially graph-capturable)
// ---------------------------------------------------------------------------
__device__ int   g_hop0[NH0];                  // hop-0 node ids        [B*S2]
__device__ float g_neigh1[(size_t)NH0 * FDIM]; // mean of hop-1 feats   [B*S2, F]
__device__ float g_fh0m[(size_t)NB * FDIM];    // mean of hop-0 feats   [B, F]
__device__ float g_fm1[(size_t)NH0 * H2];      // featmap1              [B*S2, 2H]
__device__ float g_fm0[(size_t)NB * H2];       // featmap0              [B, 2H]
__device__ float g_x1[(size_t)NB * H2];        // mean(featmap1)        [B, 2H]
__device__ float g_preln[(size_t)NB * H2];     // agg2 pre-layernorm    [B, 2H]

// ---------------------------------------------------------------------------
// K1: hop0[i*S2+j] = adj[x[i]*D + perm0[j]]
// ---------------------------------------------------------------------------
__global__ void hop0_kernel(const int* __restrict__ x,
                            const int* __restrict__ adj,
                            const int* __restrict__ perm0) {
    int t = blockIdx.x * blockDim.x + threadIdx.x;
    if (t >= NH0) return;
    int i = t / S2N, j = t % S2N;
    g_hop0[t] = adj[(size_t)x[i] * DADJ + perm0[j]];
}

// ---------------------------------------------------------------------------
// K2: neigh1[r] = mean_{s<25} features[ adj[hop0[r]*D + perm1[s]] ]
// One block per r. Memory-bound random-row gather (the big HBM consumer).
// ---------------------------------------------------------------------------
__global__ __launch_bounds__(256) void neigh_mean_kernel(
    const int* __restrict__ adj, const int* __restrict__ perm1,
    const float* __restrict__ feat) {
    int r = blockIdx.x;
    __shared__ int ids[S1N];
    int tid = threadIdx.x;
    if (tid < S1N) ids[tid] = adj[(size_t)g_hop0[r] * DADJ + perm1[tid]];
    __syncthreads();

    float2 a0 = make_float2(0.f, 0.f);
    float2 a1 = make_float2(0.f, 0.f);
    // FDIM=602 floats = 301 float2 slots; rows are 8-byte aligned
#pragma unroll 1
    for (int s = 0; s < S1N; s++) {
        const float2* fp = (const float2*)(feat + (size_t)ids[s] * FDIM);
        float2 v = fp[tid];
        a0.x += v.x; a0.y += v.y;
        if (tid < 45) { float2 u = fp[tid + 256]; a1.x += u.x; a1.y += u.y; }
    }
    const float sc = 1.f / S1N;
    float2* op = (float2*)(g_neigh1 + (size_t)r * FDIM);
    op[tid] = make_float2(a0.x * sc, a0.y * sc);
    if (tid < 45) op[tid + 256] = make_float2(a1.x * sc, a1.y * sc);
}

// ---------------------------------------------------------------------------
// K3: fh0m[i] = mean_{j<10} features[hop0[i*10+j]]
// ---------------------------------------------------------------------------
__global__ __launch_bounds__(256) void fh0_mean_kernel(const float* __restrict__ feat) {
    int i = blockIdx.x;
    __shared__ int ids[S2N];
    int tid = threadIdx.x;
    if (tid < S2N) ids[tid] = g_hop0[i * S2N + tid];
    __syncthreads();

    float2 a0 = make_float2(0.f, 0.f);
    float2 a1 = make_float2(0.f, 0.f);
#pragma unroll 1
    for (int s = 0; s < S2N; s++) {
        const float2* fp = (const float2*)(feat + (size_t)ids[s] * FDIM);
        float2 v = fp[tid];
        a0.x += v.x; a0.y += v.y;
        if (tid < 45) { float2 u = fp[tid + 256]; a1.x += u.x; a1.y += u.y; }
    }
    const float sc = 1.f / S2N;
    float2* op = (float2*)(g_fh0m + (size_t)i * FDIM);
    op[tid] = make_float2(a0.x * sc, a0.y * sc);
    if (tid < 45) op[tid + 256] = make_float2(a1.x * sc, a1.y * sc);
}

// ---------------------------------------------------------------------------
// Tiled SGEMM: Cdst[:, coff:coff+256] = act(A @ W^T + bias)
//   A selected at compile time:
//     ASEL 0: feat gathered by row index (RSEL 0: x arg, RSEL 1: g_hop0)
//     ASEL 1: g_neigh1   ASEL 2: g_fh0m   ASEL 3: g_fm0   ASEL 4: g_x1
//   CSEL 0: g_fm1   CSEL 1: g_fm0   CSEL 2: g_preln
//   Tile 128x64x16, 256 threads, 8x4 accum per thread.
// ---------------------------------------------------------------------------
template <bool RELU, int ASEL, int RSEL, int CSEL>
__global__ __launch_bounds__(256) void gemm_bias_kernel(
    const float* __restrict__ feat, const int* __restrict__ xidx,
    const float* __restrict__ W, const float* __restrict__ bias,
    int K, int lda, int coff) {
    constexpr int BM = 128, BN = 64, BK = 16, TM = 8, TN = 4;
    __shared__ float As[BK][BM + 4];   // +4 pad keeps float4 alignment, breaks conflicts
    __shared__ float Ws[BK][BN];

    const float* A;
    const int* ridx = nullptr;
    if constexpr (ASEL == 0) { A = feat; ridx = (RSEL == 1) ? g_hop0 : xidx; }
    else if constexpr (ASEL == 1) A = g_neigh1;
    else if constexpr (ASEL == 2) A = g_fh0m;
    else if constexpr (ASEL == 3) A = g_fm0;
    else                          A = g_x1;
    float* C;
    if constexpr (CSEL == 0)      C = g_fm1;
    else if constexpr (CSEL == 1) C = g_fm0;
    else                          C = g_preln;

    const int tid = threadIdx.x;
    const int tx = tid & 15, ty = tid >> 4;       // 16x16 thread grid
    const int brow = blockIdx.y * BM, bcol = blockIdx.x * BN;

    // Each thread loads A rows {i*16+ty}, column k0+tx. Pre-resolve gather rows.
    int ga[8];
#pragma unroll
    for (int i = 0; i < 8; i++) {
        int row = brow + i * 16 + ty;
        ga[i] = (ASEL == 0) ? ridx[row] : row;
    }

    float acc[TM][TN];
#pragma unroll
    for (int i = 0; i < TM; i++)
#pragma unroll
        for (int j = 0; j < TN; j++) acc[i][j] = 0.f;

    for (int k0 = 0; k0 < K; k0 += BK) {
        const bool kp = (k0 + tx) < K;
#pragma unroll
        for (int i = 0; i < 8; i++) {
            float v = kp ? A[(size_t)ga[i] * lda + k0 + tx] : 0.f;
            As[tx][i * 16 + ty] = v;
        }
#pragma unroll
        for (int i = 0; i < 4; i++) {
            int n = i * 16 + ty;
            float v = kp ? W[(size_t)(bcol + n) * K + k0 + tx] : 0.f;
            Ws[tx][n] = v;
        }
        __syncthreads();
#pragma unroll
        for (int k = 0; k < BK; k++) {
            float a[TM], b[TN];
            float4 v0 = *(const float4*)&As[k][ty * TM];
            float4 v1 = *(const float4*)&As[k][ty * TM + 4];
            a[0] = v0.x; a[1] = v0.y; a[2] = v0.z; a[3] = v0.w;
            a[4] = v1.x; a[5] = v1.y; a[6] = v1.z; a[7] = v1.w;
            float4 w0 = *(const float4*)&Ws[k][tx * TN];
            b[0] = w0.x; b[1] = w0.y; b[2] = w0.z; b[3] = w0.w;
#pragma unroll
            for (int i = 0; i < TM; i++)
#pragma unroll
                for (int j = 0; j < TN; j++)
                    acc[i][j] = fmaf(a[i], b[j], acc[i][j]);
        }
        __syncthreads();
    }

#pragma unroll
    for (int i = 0; i < TM; i++) {
        int row = brow + ty * TM + i;
        float* cp = C + (size_t)row * H2 + coff + bcol + tx * TN;
#pragma unroll
        for (int j = 0; j < TN; j++) {
            float v = acc[i][j] + bias[bcol + tx * TN + j];
            if (RELU) v = fmaxf(v, 0.f);
            cp[j] = v;
        }
    }
}

// ---------------------------------------------------------------------------
// K5: x1[i] = mean_{j<10} featmap1[i*10+j]
// ---------------------------------------------------------------------------
__global__ __launch_bounds__(256) void x1_mean_kernel() {
    int i = blockIdx.x, c = threadIdx.x;
    float s0 = 0.f, s1 = 0.f;
#pragma unroll
    for (int j = 0; j < S2N; j++) {
        const float* p = g_fm1 + (size_t)(i * S2N + j) * H2;
        s0 += p[c];
        s1 += p[c + 256];
    }
    g_x1[(size_t)i * H2 + c]       = s0 * (1.f / S2N);
    g_x1[(size_t)i * H2 + c + 256] = s1 * (1.f / S2N);
}

// ---------------------------------------------------------------------------
// K8: fused LayerNorm (eps=1e-12) + classifier  [1024 blocks x 256 threads]
// ---------------------------------------------------------------------------
__global__ __launch_bounds__(256) void ln_cls_kernel(
    const float* __restrict__ ln_g, const float* __restrict__ ln_b,
    const float* __restrict__ wc, const float* __restrict__ bc,
    float* __restrict__ out) {
    int r = blockIdx.x, tid = threadIdx.x;
    __shared__ float srow[H2];
    __shared__ float rs1[8], rs2[8];

    float v0 = g_preln[(size_t)r * H2 + tid];
    float v1 = g_preln[(size_t)r * H2 + tid + 256];
    float s1 = v0 + v1, s2 = v0 * v0 + v1 * v1;
#pragma unroll
    for (int o = 16; o; o >>= 1) {
        s1 += __shfl_xor_sync(0xffffffffu, s1, o);
        s2 += __shfl_xor_sync(0xffffffffu, s2, o);
    }
    int lane = tid & 31, w = tid >> 5;
    if (lane == 0) { rs1[w] = s1; rs2[w] = s2; }
    __syncthreads();
    float T1 = 0.f, T2 = 0.f;
#pragma unroll
    for (int i = 0; i < 8; i++) { T1 += rs1[i]; T2 += rs2[i]; }
    float mu   = T1 * (1.f / H2);
    float var  = T2 * (1.f / H2) - mu * mu;
    float rstd = rsqrtf(var + 1e-12f);

    srow[tid]       = (v0 - mu) * rstd * ln_g[tid]       + ln_b[tid];
    srow[tid + 256] = (v1 - mu) * rstd * ln_g[tid + 256] + ln_b[tid + 256];
    __syncthreads();

    // classifier: warp w handles output classes w, w+8, ...
    for (int c = w; c < NCLS; c += 8) {
        float p = 0.f;
        for (int f = lane; f < H2; f += 32)
            p = fmaf(srow[f], wc[(size_t)c * H2 + f], p);
#pragma unroll
        for (int o = 16; o; o >>= 1) p += __shfl_xor_sync(0xffffffffu, p, o);
        if (lane == 0) out[(size_t)r * NCLS + c] = p + bc[c];
    }
}

// ---------------------------------------------------------------------------
// Launch — kernel launches ONLY (graph-capturable, no runtime API calls)
// ---------------------------------------------------------------------------
extern "C" void kernel_launch(void* const* d_in, const int* in_sizes, int n_in,
                              void* d_out, int out_size) {
    const int*   x     = (const int*)d_in[0];
    const int*   adj   = (const int*)d_in[1];
    const int*   perm0 = (const int*)d_in[2];
    const int*   perm1 = (const int*)d_in[3];
    const float* feat  = (const float*)d_in[4];
    const float* w1a_s = (const float*)d_in[5];
    const float* b1a_s = (const float*)d_in[6];
    const float* w1a_n = (const float*)d_in[7];
    const float* b1a_n = (const float*)d_in[8];
    const float* w1b_s = (const float*)d_in[9];
    const float* b1b_s = (const float*)d_in[10];
    const float* w1b_n = (const float*)d_in[11];
    const float* b1b_n = (const float*)d_in[12];
    const float* w2_s  = (const float*)d_in[13];
    const float* b2_s  = (const float*)d_in[14];
    const float* w2_n  = (const float*)d_in[15];
    const float* b2_n  = (const float*)d_in[16];
    const float* ln_g  = (const float*)d_in[17];
    const float* ln_b  = (const float*)d_in[18];
    const float* w_cls = (const float*)d_in[19];
    const float* b_cls = (const float*)d_in[20];
    float* out = (float*)d_out;

    // 1) sampling + gather/means
    hop0_kernel<<<(NH0 + 255) / 256, 256>>>(x, adj, perm0);
    neigh_mean_kernel<<<NH0, 256>>>(adj, perm1, feat);
    fh0_mean_kernel<<<NB, 256>>>(feat);

    // 2) featmap1 = relu([feat[hop0] @ w1b_self^T | neigh1 @ w1b_neigh^T] + b)
    gemm_bias_kernel<true, 0, 1, 0><<<dim3(4, 80), 256>>>(
        feat, nullptr, w1b_s, b1b_s, FDIM, FDIM, 0);
    gemm_bias_kernel<true, 1, 0, 0><<<dim3(4, 80), 256>>>(
        feat, nullptr, w1b_n, b1b_n, FDIM, FDIM, HDIM);

    // 3) featmap0 = relu([feat[x] @ w1a_self^T | fh0m @ w1a_neigh^T] + b)
    gemm_bias_kernel<true, 0, 0, 1><<<dim3(4, 8), 256>>>(
        feat, x, w1a_s, b1a_s, FDIM, FDIM, 0);
    gemm_bias_kernel<true, 2, 0, 1><<<dim3(4, 8), 256>>>(
        feat, nullptr, w1a_n, b1a_n, FDIM, FDIM, HDIM);

    // 4) x1 = mean over S2 of featmap1
    x1_mean_kernel<<<NB, 256>>>();

    // 5) agg2: preln = [featmap0 @ w2_self^T + b | x1 @ w2_neigh^T + b]
    gemm_bias_kernel<false, 3, 0, 2><<<dim3(4, 8), 256>>>(
        feat, nullptr, w2_s, b2_s, H2, H2, 0);
    gemm_bias_kernel<false, 4, 0, 2><<<dim3(4, 8), 256>>>(
        feat, nullptr, w2_n, b2_n, H2, H2, HDIM);

    // 6) layernorm + classifier
    ln_cls_kernel<<<NB, 256>>>(ln_g, ln_b, w_cls, b_cls, out);
}

// round 4
// speedup vs baseline: 1.4378x; 1.4378x over previous
#include <cuda_runtime.h>
#include <cstdint>

// Problem constants
#define NNODES 200000
#define FDIM   602
#define DADJ   128
#define HDIM   256
#define NCLS   41
#define NB     1024
#define S1N    25
#define S2N    10
#define NH0    (NB * S2N)   // 10240
#define H2     (2 * HDIM)   // 512

// ---------------------------------------------------------------------------
// Scratch (allocation-free: __device__ globals, referenced directly from
// device code — kernel_launch makes NO runtime API calls besides launches)
// ---------------------------------------------------------------------------
__device__ int   g_hop0[NH0];                  // hop-0 node ids        [B*S2]
__device__ float g_neigh1[(size_t)NH0 * FDIM]; // mean of hop-1 feats   [B*S2, F]
__device__ float g_fh0m[(size_t)NB * FDIM];    // mean of hop-0 feats   [B, F]
__device__ float g_fm1[(size_t)NH0 * H2];      // featmap1              [B*S2, 2H]
__device__ float g_fm0[(size_t)NB * H2];       // featmap0              [B, 2H]
__device__ float g_x1[(size_t)NB * H2];        // mean(featmap1)        [B, 2H]
__device__ float g_preln[(size_t)NB * H2];     // agg2 pre-layernorm    [B, 2H]

// ---------------------------------------------------------------------------
// K1: hop0[i*S2+j] = adj[x[i]*D + perm0[j]]
// ---------------------------------------------------------------------------
__global__ void hop0_kernel(const int* __restrict__ x,
                            const int* __restrict__ adj,
                            const int* __restrict__ perm0) {
    int t = blockIdx.x * blockDim.x + threadIdx.x;
    if (t >= NH0) return;
    int i = t / S2N, j = t % S2N;
    g_hop0[t] = adj[(size_t)x[i] * DADJ + perm0[j]];
}

// ---------------------------------------------------------------------------
// K2: neigh1[r] = mean_{s<25} features[ adj[hop0[r]*D + perm1[s]] ]
// ---------------------------------------------------------------------------
__global__ __launch_bounds__(256) void neigh_mean_kernel(
    const int* __restrict__ adj, const int* __restrict__ perm1,
    const float* __restrict__ feat) {
    int r = blockIdx.x;
    __shared__ int ids[S1N];
    int tid = threadIdx.x;
    if (tid < S1N) ids[tid] = adj[(size_t)g_hop0[r] * DADJ + perm1[tid]];
    __syncthreads();

    float2 a0 = make_float2(0.f, 0.f);
    float2 a1 = make_float2(0.f, 0.f);
#pragma unroll 1
    for (int s = 0; s < S1N; s++) {
        const float2* fp = (const float2*)(feat + (size_t)ids[s] * FDIM);
        float2 v = fp[tid];
        a0.x += v.x; a0.y += v.y;
        if (tid < 45) { float2 u = fp[tid + 256]; a1.x += u.x; a1.y += u.y; }
    }
    const float sc = 1.f / S1N;
    float2* op = (float2*)(g_neigh1 + (size_t)r * FDIM);
    op[tid] = make_float2(a0.x * sc, a0.y * sc);
    if (tid < 45) op[tid + 256] = make_float2(a1.x * sc, a1.y * sc);
}

// ---------------------------------------------------------------------------
// K3: fh0m[i] = mean_{j<10} features[hop0[i*10+j]]
// ---------------------------------------------------------------------------
__global__ __launch_bounds__(256) void fh0_mean_kernel(const float* __restrict__ feat) {
    int i = blockIdx.x;
    __shared__ int ids[S2N];
    int tid = threadIdx.x;
    if (tid < S2N) ids[tid] = g_hop0[i * S2N + tid];
    __syncthreads();

    float2 a0 = make_float2(0.f, 0.f);
    float2 a1 = make_float2(0.f, 0.f);
#pragma unroll 1
    for (int s = 0; s < S2N; s++) {
        const float2* fp = (const float2*)(feat + (size_t)ids[s] * FDIM);
        float2 v = fp[tid];
        a0.x += v.x; a0.y += v.y;
        if (tid < 45) { float2 u = fp[tid + 256]; a1.x += u.x; a1.y += u.y; }
    }
    const float sc = 1.f / S2N;
    float2* op = (float2*)(g_fh0m + (size_t)i * FDIM);
    op[tid] = make_float2(a0.x * sc, a0.y * sc);
    if (tid < 45) op[tid + 256] = make_float2(a1.x * sc, a1.y * sc);
}

// ---------------------------------------------------------------------------
// tf32 tensor-core GEMM: C[:, coff:coff+256] = act(A @ W^T + bias)
//   A selected at compile time:
//     ASEL 0: feat gathered by row index (RSEL 0: xidx arg, RSEL 1: g_hop0)
//     ASEL 1: g_neigh1   ASEL 2: g_fh0m   ASEL 3: g_fm0   ASEL 4: g_x1
//   CSEL 0: g_fm1   CSEL 1: g_fm0   CSEL 2: g_preln
//   Tile 128x128x16, 8 warps (2M x 4N), warp tile 64x32,
//   mma.sync.m16n8k8 tf32, cp.async double-buffered smem.
//   Requires: M % 128 == 0, N tile = 128 (weights have 256 rows), K even.
// ---------------------------------------------------------------------------
__device__ __forceinline__ void cp8(uint32_t dst, const void* src, int sz) {
    asm volatile("cp.async.ca.shared.global [%0], [%1], 8, %2;\n"
                 :: "r"(dst), "l"(src), "r"(sz));
}
__device__ __forceinline__ void mma_tf32(float* c, const uint32_t* a, const uint32_t* b) {
    asm volatile(
        "mma.sync.aligned.m16n8k8.row.col.f32.tf32.tf32.f32 "
        "{%0,%1,%2,%3}, {%4,%5,%6,%7}, {%8,%9}, {%0,%1,%2,%3};"
        : "+f"(c[0]), "+f"(c[1]), "+f"(c[2]), "+f"(c[3])
        : "r"(a[0]), "r"(a[1]), "r"(a[2]), "r"(a[3]), "r"(b[0]), "r"(b[1]));
}

template <bool RELU, int ASEL, int RSEL, int CSEL>
__global__ __launch_bounds__(256, 2) void gemm_tf32_kernel(
    const float* __restrict__ feat, const int* __restrict__ xidx,
    const float* __restrict__ W, const float* __restrict__ bias,
    int K, int lda, int coff) {
    constexpr int BM = 128, BN = 128, BK = 16, PAD = 18;
    __shared__ float As[2][BM * PAD];
    __shared__ float Ws[2][BN * PAD];

    const float* A;
    const int* ridx = nullptr;
    if constexpr (ASEL == 0) { A = feat; ridx = (RSEL == 1) ? g_hop0 : xidx; }
    else if constexpr (ASEL == 1) A = g_neigh1;
    else if constexpr (ASEL == 2) A = g_fh0m;
    else if constexpr (ASEL == 3) A = g_fm0;
    else                          A = g_x1;
    float* C;
    if constexpr (CSEL == 0)      C = g_fm1;
    else if constexpr (CSEL == 1) C = g_fm0;
    else                          C = g_preln;

    const int tid = threadIdx.x, lane = tid & 31, wid = tid >> 5;
    const int wm = wid & 1, wn = wid >> 1;        // warp at (wm*64, wn*32)
    const int brow = blockIdx.y * BM, bcol = blockIdx.x * BN;

    // ---- loader: thread t handles row (t>>1) of both A and W tiles,
    //      float2 slots (t&1)*4 .. +3 (16 floats per row per stage) ----
    const int lrow = tid >> 1;
    const int lslot = (tid & 1) * 4;
    int arow = brow + lrow;
    int grow = (ASEL == 0) ? ridx[arow] : arow;
    const float2* aRow = (const float2*)(A + (size_t)grow * lda);
    const float2* wRow = (const float2*)(W + (size_t)(bcol + lrow) * K);
    const int kmax2 = K >> 1;  // K is even (602 or 512)

    uint32_t sA0 = (uint32_t)__cvta_generic_to_shared(&As[0][lrow * PAD + (tid & 1) * 8]);
    uint32_t sW0 = (uint32_t)__cvta_generic_to_shared(&Ws[0][lrow * PAD + (tid & 1) * 8]);
    const uint32_t bufStride = (uint32_t)(BM * PAD * 4);

    auto load_stage = [&](int buf, int k0) {
        int f2base = (k0 >> 1) + lslot;
        uint32_t dA = sA0 + buf * bufStride;
        uint32_t dW = sW0 + buf * bufStride;
#pragma unroll
        for (int c = 0; c < 4; c++) {
            int f2 = f2base + c;
            int sz = (f2 < kmax2) ? 8 : 0;
            int fs = (f2 < kmax2) ? f2 : (kmax2 - 1);
            cp8(dA + c * 8, aRow + fs, sz);
            cp8(dW + c * 8, wRow + fs, sz);
        }
        asm volatile("cp.async.commit_group;\n");
    };

    float acc[4][4][4];
#pragma unroll
    for (int mt = 0; mt < 4; mt++)
#pragma unroll
        for (int nt = 0; nt < 4; nt++)
#pragma unroll
            for (int i = 0; i < 4; i++) acc[mt][nt][i] = 0.f;

    const int nkt = (K + BK - 1) / BK;
    load_stage(0, 0);

    const int qrow = lane >> 2, qcol = lane & 3;

    for (int t = 0; t < nkt; t++) {
        if (t + 1 < nkt) {
            load_stage((t + 1) & 1, (t + 1) * BK);
            asm volatile("cp.async.wait_group 1;\n");
        } else {
            asm volatile("cp.async.wait_group 0;\n");
        }
        __syncthreads();

        const float* a_s = As[t & 1];
        const float* w_s = Ws[t & 1];
#pragma unroll
        for (int kk = 0; kk < 2; kk++) {
            const int kbase = kk * 8 + qcol;
            uint32_t af[4][4], bf[4][2];
#pragma unroll
            for (int mt = 0; mt < 4; mt++) {
                int m = wm * 64 + mt * 16 + qrow;
                af[mt][0] = __float_as_uint(a_s[m * PAD + kbase]);
                af[mt][1] = __float_as_uint(a_s[(m + 8) * PAD + kbase]);
                af[mt][2] = __float_as_uint(a_s[m * PAD + kbase + 4]);
                af[mt][3] = __float_as_uint(a_s[(m + 8) * PAD + kbase + 4]);
            }
#pragma unroll
            for (int nt = 0; nt < 4; nt++) {
                int n = wn * 32 + nt * 8 + qrow;
                bf[nt][0] = __float_as_uint(w_s[n * PAD + kbase]);
                bf[nt][1] = __float_as_uint(w_s[n * PAD + kbase + 4]);
            }
#pragma unroll
            for (int mt = 0; mt < 4; mt++)
#pragma unroll
                for (int nt = 0; nt < 4; nt++)
                    mma_tf32(acc[mt][nt], af[mt], bf[nt]);
        }
        __syncthreads();
    }

    // ---- epilogue: bias + activation, direct global store ----
#pragma unroll
    for (int mt = 0; mt < 4; mt++) {
        int row = brow + wm * 64 + mt * 16 + qrow;
#pragma unroll
        for (int nt = 0; nt < 4; nt++) {
            int colb = bcol + wn * 32 + nt * 8 + qcol * 2;
            float b0 = bias[colb], b1 = bias[colb + 1];
            float v0 = acc[mt][nt][0] + b0;
            float v1 = acc[mt][nt][1] + b1;
            float v2 = acc[mt][nt][2] + b0;
            float v3 = acc[mt][nt][3] + b1;
            if (RELU) {
                v0 = fmaxf(v0, 0.f); v1 = fmaxf(v1, 0.f);
                v2 = fmaxf(v2, 0.f); v3 = fmaxf(v3, 0.f);
            }
            float* p0 = C + (size_t)row * H2 + coff + colb;
            float* p1 = C + (size_t)(row + 8) * H2 + coff + colb;
            p0[0] = v0; p0[1] = v1;
            p1[0] = v2; p1[1] = v3;
        }
    }
}

// ---------------------------------------------------------------------------
// K5: x1[i] = mean_{j<10} featmap1[i*10+j]
// ---------------------------------------------------------------------------
__global__ __launch_bounds__(256) void x1_mean_kernel() {
    int i = blockIdx.x, c = threadIdx.x;
    float s0 = 0.f, s1 = 0.f;
#pragma unroll
    for (int j = 0; j < S2N; j++) {
        const float* p = g_fm1 + (size_t)(i * S2N + j) * H2;
        s0 += p[c];
        s1 += p[c + 256];
    }
    g_x1[(size_t)i * H2 + c]       = s0 * (1.f / S2N);
    g_x1[(size_t)i * H2 + c + 256] = s1 * (1.f / S2N);
}

// ---------------------------------------------------------------------------
// K8: fused LayerNorm (eps=1e-12) + classifier  [1024 blocks x 256 threads]
// ---------------------------------------------------------------------------
__global__ __launch_bounds__(256) void ln_cls_kernel(
    const float* __restrict__ ln_g, const float* __restrict__ ln_b,
    const float* __restrict__ wc, const float* __restrict__ bc,
    float* __restrict__ out) {
    int r = blockIdx.x, tid = threadIdx.x;
    __shared__ float srow[H2];
    __shared__ float rs1[8], rs2[8];

    float v0 = g_preln[(size_t)r * H2 + tid];
    float v1 = g_preln[(size_t)r * H2 + tid + 256];
    float s1 = v0 + v1, s2 = v0 * v0 + v1 * v1;
#pragma unroll
    for (int o = 16; o; o >>= 1) {
        s1 += __shfl_xor_sync(0xffffffffu, s1, o);
        s2 += __shfl_xor_sync(0xffffffffu, s2, o);
    }
    int lane = tid & 31, w = tid >> 5;
    if (lane == 0) { rs1[w] = s1; rs2[w] = s2; }
    __syncthreads();
    float T1 = 0.f, T2 = 0.f;
#pragma unroll
    for (int i = 0; i < 8; i++) { T1 += rs1[i]; T2 += rs2[i]; }
    float mu   = T1 * (1.f / H2);
    float var  = T2 * (1.f / H2) - mu * mu;
    float rstd = rsqrtf(var + 1e-12f);

    srow[tid]       = (v0 - mu) * rstd * ln_g[tid]       + ln_b[tid];
    srow[tid + 256] = (v1 - mu) * rstd * ln_g[tid + 256] + ln_b[tid + 256];
    __syncthreads();

    for (int c = w; c < NCLS; c += 8) {
        float p = 0.f;
        for (int f = lane; f < H2; f += 32)
            p = fmaf(srow[f], wc[(size_t)c * H2 + f], p);
#pragma unroll
        for (int o = 16; o; o >>= 1) p += __shfl_xor_sync(0xffffffffu, p, o);
        if (lane == 0) out[(size_t)r * NCLS + c] = p + bc[c];
    }
}

// ---------------------------------------------------------------------------
// Launch — kernel launches ONLY (graph-capturable, no runtime API calls)
// ---------------------------------------------------------------------------
extern "C" void kernel_launch(void* const* d_in, const int* in_sizes, int n_in,
                              void* d_out, int out_size) {
    const int*   x     = (const int*)d_in[0];
    const int*   adj   = (const int*)d_in[1];
    const int*   perm0 = (const int*)d_in[2];
    const int*   perm1 = (const int*)d_in[3];
    const float* feat  = (const float*)d_in[4];
    const float* w1a_s = (const float*)d_in[5];
    const float* b1a_s = (const float*)d_in[6];
    const float* w1a_n = (const float*)d_in[7];
    const float* b1a_n = (const float*)d_in[8];
    const float* w1b_s = (const float*)d_in[9];
    const float* b1b_s = (const float*)d_in[10];
    const float* w1b_n = (const float*)d_in[11];
    const float* b1b_n = (const float*)d_in[12];
    const float* w2_s  = (const float*)d_in[13];
    const float* b2_s  = (const float*)d_in[14];
    const float* w2_n  = (const float*)d_in[15];
    const float* b2_n  = (const float*)d_in[16];
    const float* ln_g  = (const float*)d_in[17];
    const float* ln_b  = (const float*)d_in[18];
    const float* w_cls = (const float*)d_in[19];
    const float* b_cls = (const float*)d_in[20];
    float* out = (float*)d_out;

    // 1) sampling + gather/means
    hop0_kernel<<<(NH0 + 255) / 256, 256>>>(x, adj, perm0);
    neigh_mean_kernel<<<NH0, 256>>>(adj, perm1, feat);
    fh0_mean_kernel<<<NB, 256>>>(feat);

    // 2) featmap1 = relu([feat[hop0] @ w1b_self^T | neigh1 @ w1b_neigh^T] + b)
    gemm_tf32_kernel<true, 0, 1, 0><<<dim3(2, 80), 256>>>(
        feat, nullptr, w1b_s, b1b_s, FDIM, FDIM, 0);
    gemm_tf32_kernel<true, 1, 0, 0><<<dim3(2, 80), 256>>>(
        feat, nullptr, w1b_n, b1b_n, FDIM, FDIM, HDIM);

    // 3) featmap0 = relu([feat[x] @ w1a_self^T | fh0m @ w1a_neigh^T] + b)
    gemm_tf32_kernel<true, 0, 0, 1><<<dim3(2, 8), 256>>>(
        feat, x, w1a_s, b1a_s, FDIM, FDIM, 0);
    gemm_tf32_kernel<true, 2, 0, 1><<<dim3(2, 8), 256>>>(
        feat, nullptr, w1a_n, b1a_n, FDIM, FDIM, HDIM);

    // 4) x1 = mean over S2 of featmap1
    x1_mean_kernel<<<NB, 256>>>();

    // 5) agg2: preln = [featmap0 @ w2_self^T + b | x1 @ w2_neigh^T + b]
    gemm_tf32_kernel<false, 3, 0, 2><<<dim3(2, 8), 256>>>(
        feat, nullptr, w2_s, b2_s, H2, H2, 0);
    gemm_tf32_kernel<false, 4, 0, 2><<<dim3(2, 8), 256>>>(
        feat, nullptr, w2_n, b2_n, H2, H2, HDIM);

    // 6) layernorm + classifier
    ln_cls_kernel<<<NB, 256>>>(ln_g, ln_b, w_cls, b_cls, out);
}

// round 7
// speedup vs baseline: 2.6271x; 1.8272x over previous
#include <cuda_runtime.h>
#include <cstdint>

// Problem constants
#define NNODES 200000
#define FDIM   602
#define DADJ   128
#define HDIM   256
#define NCLS   41
#define NB     1024
#define S1N    25
#define S2N    10
#define NH0    (NB * S2N)   // 10240
#define H2     (2 * HDIM)   // 512

// ---------------------------------------------------------------------------
// Scratch (allocation-free __device__ globals; kernel_launch makes NO runtime
// API calls besides kernel launches -> trivially graph-capturable)
// ---------------------------------------------------------------------------
__device__ int   g_hop0[NH0];                  // hop-0 node ids        [B*S2]
__device__ float g_neigh1[(size_t)NH0 * FDIM]; // mean of hop-1 feats   [B*S2, F]
__device__ float g_fh0m[(size_t)NB * FDIM];    // mean of hop-0 feats   [B, F]
__device__ float g_fm1[(size_t)NH0 * H2];      // featmap1              [B*S2, 2H]
__device__ float g_fm0[(size_t)NB * H2];       // featmap0              [B, 2H]
__device__ float g_x1[(size_t)NB * H2];        // mean(featmap1)        [B, 2H]
__device__ float g_preln[(size_t)NB * H2];     // agg2 pre-layernorm    [B, 2H]

// ---------------------------------------------------------------------------
// K1: neigh1[r] = mean_{s<25} features[ adj[hop0[r]*D + perm1[s]] ]
//     also computes hop0[r] = adj[x[r/10]*D + perm0[r%10]] inline
// ---------------------------------------------------------------------------
__global__ __launch_bounds__(320) void neigh_mean_kernel(
    const int* __restrict__ x, const int* __restrict__ adj,
    const int* __restrict__ perm0, const int* __restrict__ perm1,
    const float* __restrict__ feat) {
    int r = blockIdx.x;
    __shared__ int ids[S1N];
    __shared__ int hop0s;
    int tid = threadIdx.x;
    if (tid == 0) {
        int i = r / S2N, j = r % S2N;
        int h = adj[(size_t)x[i] * DADJ + perm0[j]];
        hop0s = h;
        g_hop0[r] = h;
    }
    __syncthreads();
    if (tid < S1N) ids[tid] = adj[(size_t)hop0s * DADJ + perm1[tid]];
    __syncthreads();

    if (tid < 301) {   // FDIM=602 floats = 301 float2 slots (rows 8B aligned)
        float2 a = make_float2(0.f, 0.f);
#pragma unroll 5
        for (int s = 0; s < S1N; s++) {
            float2 v = ((const float2*)(feat + (size_t)ids[s] * FDIM))[tid];
            a.x += v.x; a.y += v.y;
        }
        const float sc = 1.f / S1N;
        ((float2*)(g_neigh1 + (size_t)r * FDIM))[tid] = make_float2(a.x * sc, a.y * sc);
    }
}

// ---------------------------------------------------------------------------
// K2: fh0m[i] = mean_{j<10} features[ adj[x[i]*D + perm0[j]] ]
// ---------------------------------------------------------------------------
__global__ __launch_bounds__(320) void fh0_mean_kernel(
    const int* __restrict__ x, const int* __restrict__ adj,
    const int* __restrict__ perm0, const float* __restrict__ feat) {
    int i = blockIdx.x;
    __shared__ int ids[S2N];
    int tid = threadIdx.x;
    if (tid < S2N) ids[tid] = adj[(size_t)x[i] * DADJ + perm0[tid]];
    __syncthreads();

    if (tid < 301) {
        float2 a = make_float2(0.f, 0.f);
#pragma unroll
        for (int s = 0; s < S2N; s++) {
            float2 v = ((const float2*)(feat + (size_t)ids[s] * FDIM))[tid];
            a.x += v.x; a.y += v.y;
        }
        const float sc = 1.f / S2N;
        ((float2*)(g_fh0m + (size_t)i * FDIM))[tid] = make_float2(a.x * sc, a.y * sc);
    }
}

// ---------------------------------------------------------------------------
// Fused tf32 tensor-core GEMM batch.
//   BATCH 1 (K=602, ReLU): 4 jobs over blockIdx.y:
//     [0,80):   fm1[:, 0:256]   = relu(feat[g_hop0] @ wA^T + biA)
//     [80,160): fm1[:, 256:512] = relu(g_neigh1    @ wB^T + biB)
//     [160,168):fm0[:, 0:256]   = relu(feat[x]     @ wC^T + biC)
//     [168,176):fm0[:, 256:512] = relu(g_fh0m      @ wD^T + biD)
//   BATCH 2 (K=512, no act): 2 jobs:
//     [0,8):  preln[:, 0:256]   = g_fm0 @ wA^T + biA
//     [8,16): preln[:, 256:512] = g_x1  @ wB^T + biB
//   Tile 128x64x16, 8 warps (4M x 2N), warp tile 32x32, mma.m16n8k8.tf32,
//   3-stage cp.async pipeline, one __syncthreads per k-tile.
// ---------------------------------------------------------------------------
__device__ __forceinline__ void cp8(uint32_t dst, const void* src, int sz) {
    asm volatile("cp.async.ca.shared.global [%0], [%1], 8, %2;\n"
                 :: "r"(dst), "l"(src), "r"(sz));
}
__device__ __forceinline__ void mma_tf32(float* c, const uint32_t* a, const uint32_t* b) {
    asm volatile(
        "mma.sync.aligned.m16n8k8.row.col.f32.tf32.tf32.f32 "
        "{%0,%1,%2,%3}, {%4,%5,%6,%7}, {%8,%9}, {%0,%1,%2,%3};"
        : "+f"(c[0]), "+f"(c[1]), "+f"(c[2]), "+f"(c[3])
        : "r"(a[0]), "r"(a[1]), "r"(a[2]), "r"(a[3]), "r"(b[0]), "r"(b[1]));
}

template <int BATCH>
__global__ __launch_bounds__(256, 3) void gemm_batch_kernel(
    const float* __restrict__ feat, const int* __restrict__ xidx,
    const float* __restrict__ wA, const float* __restrict__ biA,
    const float* __restrict__ wB, const float* __restrict__ biB,
    const float* __restrict__ wC, const float* __restrict__ biC,
    const float* __restrict__ wD, const float* __restrict__ biD) {
    constexpr int KDIM = (BATCH == 1) ? FDIM : H2;
    constexpr bool RELU = (BATCH == 1);
    constexpr int BM = 128, BN = 64, BK = 16, PAD = 18, NSTG = 3;
    constexpr int kmax2 = KDIM / 2;           // float2 chunks per row
    constexpr int nkt = (KDIM + BK - 1) / BK; // 38 or 32
    __shared__ float As[NSTG][BM * PAD];
    __shared__ float Ws[NSTG][BN * PAD];

    const int jy = blockIdx.y;
    const float* A; const int* ridx = nullptr;
    const float* W; const float* bias;
    float* C; int coff, rowbase;
    if constexpr (BATCH == 1) {
        if (jy < 80)       { A = feat;     ridx = g_hop0; W = wA; bias = biA; C = g_fm1; coff = 0;    rowbase = jy * BM; }
        else if (jy < 160) { A = g_neigh1;                W = wB; bias = biB; C = g_fm1; coff = HDIM; rowbase = (jy - 80) * BM; }
        else if (jy < 168) { A = feat;     ridx = xidx;   W = wC; bias = biC; C = g_fm0; coff = 0;    rowbase = (jy - 160) * BM; }
        else               { A = g_fh0m;                  W = wD; bias = biD; C = g_fm0; coff = HDIM; rowbase = (jy - 168) * BM; }
    } else {
        if (jy < 8) { A = g_fm0; W = wA; bias = biA; coff = 0;    rowbase = jy * BM; }
        else        { A = g_x1;  W = wB; bias = biB; coff = HDIM; rowbase = (jy - 8) * BM; }
        C = g_preln;
    }

    const int tid = threadIdx.x, lane = tid & 31, wid = tid >> 5;
    const int wm = wid & 3, wn = wid >> 2;         // warp tile (wm*32, wn*32)
    const int bcol = blockIdx.x * BN;

    // Loaders: A row = tid>>1 (chunks (tid&1)*4..+3); W row = tid>>2 (chunks (tid&3)*2..+1)
    const int aLrow = tid >> 1;
    int ga = rowbase + aLrow;
    if (ridx) ga = ridx[ga];
    const float2* aRow = (const float2*)(A + (size_t)ga * KDIM);
    const int wLrow = tid >> 2;
    const float2* wRow = (const float2*)(W + (size_t)(bcol + wLrow) * KDIM);

    const uint32_t sA = (uint32_t)__cvta_generic_to_shared(&As[0][aLrow * PAD]) + (tid & 1) * 32;
    const uint32_t sW = (uint32_t)__cvta_generic_to_shared(&Ws[0][wLrow * PAD]) + (tid & 3) * 16;
    constexpr uint32_t strideA = BM * PAD * 4, strideW = BN * PAD * 4;

    auto load_stage = [&](int buf, int k0) {
        const int f2a = (k0 >> 1) + (tid & 1) * 4;
        const int f2w = (k0 >> 1) + (tid & 3) * 2;
        const uint32_t dA = sA + buf * strideA;
        const uint32_t dW = sW + buf * strideW;
#pragma unroll
        for (int c = 0; c < 4; c++) {
            int f2 = f2a + c;
            cp8(dA + c * 8, aRow + ((f2 < kmax2) ? f2 : (kmax2 - 1)), (f2 < kmax2) ? 8 : 0);
        }
#pragma unroll
        for (int c = 0; c < 2; c++) {
            int f2 = f2w + c;
            cp8(dW + c * 8, wRow + ((f2 < kmax2) ? f2 : (kmax2 - 1)), (f2 < kmax2) ? 8 : 0);
        }
        asm volatile("cp.async.commit_group;\n");
    };

    float acc[2][4][4];
#pragma unroll
    for (int mt = 0; mt < 2; mt++)
#pragma unroll
        for (int nt = 0; nt < 4; nt++)
#pragma unroll
            for (int i = 0; i < 4; i++) acc[mt][nt][i] = 0.f;

    // prologue: stages 0,1 in flight
    load_stage(0, 0);
    load_stage(1, BK);

    const int qrow = lane >> 2, qcol = lane & 3;
    int buf = 0;
    for (int t = 0; t < nkt; t++) {
        if (t + 1 < nkt) asm volatile("cp.async.wait_group 1;\n");
        else             asm volatile("cp.async.wait_group 0;\n");
        __syncthreads();   // stage t visible; all warps done with stage t-1's buffer
        if (t + 2 < nkt) {
            int nb = buf + 2; if (nb >= NSTG) nb -= NSTG;
            load_stage(nb, (t + 2) * BK);
        }
        const float* a_s = As[buf];
        const float* w_s = Ws[buf];
#pragma unroll
        for (int kk = 0; kk < 2; kk++) {
            const int kbase = kk * 8 + qcol;
            uint32_t af[2][4], bf[4][2];
#pragma unroll
            for (int mt = 0; mt < 2; mt++) {
                int m = wm * 32 + mt * 16 + qrow;
                af[mt][0] = __float_as_uint(a_s[m * PAD + kbase]);
                af[mt][1] = __float_as_uint(a_s[(m + 8) * PAD + kbase]);
                af[mt][2] = __float_as_uint(a_s[m * PAD + kbase + 4]);
                af[mt][3] = __float_as_uint(a_s[(m + 8) * PAD + kbase + 4]);
            }
#pragma unroll
            for (int nt = 0; nt < 4; nt++) {
                int n = wn * 32 + nt * 8 + qrow;
                bf[nt][0] = __float_as_uint(w_s[n * PAD + kbase]);
                bf[nt][1] = __float_as_uint(w_s[n * PAD + kbase + 4]);
            }
#pragma unroll
            for (int mt = 0; mt < 2; mt++)
#pragma unroll
                for (int nt = 0; nt < 4; nt++)
                    mma_tf32(acc[mt][nt], af[mt], bf[nt]);
        }
        if (++buf == NSTG) buf = 0;
    }

    // Epilogue: bias + optional ReLU, direct store
#pragma unroll
    for (int mt = 0; mt < 2; mt++) {
        int row = rowbase + wm * 32 + mt * 16 + qrow;
#pragma unroll
        for (int nt = 0; nt < 4; nt++) {
            int colb = bcol + wn * 32 + nt * 8 + qcol * 2;
            float b0 = bias[colb], b1 = bias[colb + 1];
            float v0 = acc[mt][nt][0] + b0;
            float v1 = acc[mt][nt][1] + b1;
            float v2 = acc[mt][nt][2] + b0;
            float v3 = acc[mt][nt][3] + b1;
            if (RELU) {
                v0 = fmaxf(v0, 0.f); v1 = fmaxf(v1, 0.f);
                v2 = fmaxf(v2, 0.f); v3 = fmaxf(v3, 0.f);
            }
            float* p0 = C + (size_t)row * H2 + coff + colb;
            float* p1 = C + (size_t)(row + 8) * H2 + coff + colb;
            p0[0] = v0; p0[1] = v1;
            p1[0] = v2; p1[1] = v3;
        }
    }
}

// ---------------------------------------------------------------------------
// K4: x1[i] = mean_{j<10} featmap1[i*10+j]
// ---------------------------------------------------------------------------
__global__ __launch_bounds__(256) void x1_mean_kernel() {
    int i = blockIdx.x, c = threadIdx.x;
    float s0 = 0.f, s1 = 0.f;
#pragma unroll
    for (int j = 0; j < S2N; j++) {
        const float* p = g_fm1 + (size_t)(i * S2N + j) * H2;
        s0 += p[c];
        s1 += p[c + 256];
    }
    g_x1[(size_t)i * H2 + c]       = s0 * (1.f / S2N);
    g_x1[(size_t)i * H2 + c + 256] = s1 * (1.f / S2N);
}

// ---------------------------------------------------------------------------
// K6: fused LayerNorm (eps=1e-12) + classifier  [1024 blocks x 256 threads]
// ---------------------------------------------------------------------------
__global__ __launch_bounds__(256) void ln_cls_kernel(
    const float* __restrict__ ln_g, const float* __restrict__ ln_b,
    const float* __restrict__ wc, const float* __restrict__ bc,
    float* __restrict__ out) {
    int r = blockIdx.x, tid = threadIdx.x;
    __shared__ float srow[H2];
    __shared__ float rs1[8], rs2[8];

    float v0 = g_preln[(size_t)r * H2 + tid];
    float v1 = g_preln[(size_t)r * H2 + tid + 256];
    float s1 = v0 + v1, s2 = v0 * v0 + v1 * v1;
#pragma unroll
    for (int o = 16; o; o >>= 1) {
        s1 += __shfl_xor_sync(0xffffffffu, s1, o);
        s2 += __shfl_xor_sync(0xffffffffu, s2, o);
    }
    int lane = tid & 31, w = tid >> 5;
    if (lane == 0) { rs1[w] = s1; rs2[w] = s2; }
    __syncthreads();
    float T1 = 0.f, T2 = 0.f;
#pragma unroll
    for (int i = 0; i < 8; i++) { T1 += rs1[i]; T2 += rs2[i]; }
    float mu   = T1 * (1.f / H2);
    float var  = T2 * (1.f / H2) - mu * mu;
    float rstd = rsqrtf(var + 1e-12f);

    srow[tid]       = (v0 - mu) * rstd * ln_g[tid]       + ln_b[tid];
    srow[tid + 256] = (v1 - mu) * rstd * ln_g[tid + 256] + ln_b[tid + 256];
    __syncthreads();

    for (int c = w; c < NCLS; c += 8) {
        float p = 0.f;
        for (int f = lane; f < H2; f += 32)
            p = fmaf(srow[f], wc[(size_t)c * H2 + f], p);
#pragma unroll
        for (int o = 16; o; o >>= 1) p += __shfl_xor_sync(0xffffffffu, p, o);
        if (lane == 0) out[(size_t)r * NCLS + c] = p + bc[c];
    }
}

// ---------------------------------------------------------------------------
// Launch — kernel launches ONLY (graph-capturable, no runtime API calls)
// ---------------------------------------------------------------------------
extern "C" void kernel_launch(void* const* d_in, const int* in_sizes, int n_in,
                              void* d_out, int out_size) {
    const int*   x     = (const int*)d_in[0];
    const int*   adj   = (const int*)d_in[1];
    const int*   perm0 = (const int*)d_in[2];
    const int*   perm1 = (const int*)d_in[3];
    const float* feat  = (const float*)d_in[4];
    const float* w1a_s = (const float*)d_in[5];
    const float* b1a_s = (const float*)d_in[6];
    const float* w1a_n = (const float*)d_in[7];
    const float* b1a_n = (const float*)d_in[8];
    const float* w1b_s = (const float*)d_in[9];
    const float* b1b_s = (const float*)d_in[10];
    const float* w1b_n = (const float*)d_in[11];
    const float* b1b_n = (const float*)d_in[12];
    const float* w2_s  = (const float*)d_in[13];
    const float* b2_s  = (const float*)d_in[14];
    const float* w2_n  = (const float*)d_in[15];
    const float* b2_n  = (const float*)d_in[16];
    const float* ln_g  = (const float*)d_in[17];
    const float* ln_b  = (const float*)d_in[18];
    const float* w_cls = (const float*)d_in[19];
    const float* b_cls = (const float*)d_in[20];
    float* out = (float*)d_out;

    // 1) gathers + means (neigh_mean also produces g_hop0)
    neigh_mean_kernel<<<NH0, 320>>>(x, adj, perm0, perm1, feat);
    fh0_mean_kernel<<<NB, 320>>>(x, adj, perm0, feat);

    // 2) fused GEMM batch 1: fm1 (self|neigh) + fm0 (self|neigh), K=602, ReLU
    gemm_batch_kernel<1><<<dim3(4, 176), 256>>>(
        feat, x,
        w1b_s, b1b_s, w1b_n, b1b_n,
        w1a_s, b1a_s, w1a_n, b1a_n);

    // 3) x1 = mean over S2 of featmap1
    x1_mean_kernel<<<NB, 256>>>();

    // 4) fused GEMM batch 2: preln = [fm0 @ w2_s^T + b | x1 @ w2_n^T + b], K=512
    gemm_batch_kernel<2><<<dim3(4, 16), 256>>>(
        feat, x,
        w2_s, b2_s, w2_n, b2_n,
        nullptr, nullptr, nullptr, nullptr);

    // 5) layernorm + classifier
    ln_cls_kernel<<<NB, 256>>>(ln_g, ln_b, w_cls, b_cls, out);
}